// round 7
// baseline (speedup 1.0000x reference)
#include <cuda_runtime.h>
#include <cuda_fp16.h>
#include <math.h>
#include <stdint.h>

#define MTOK 4096   // B*N
#define DDIM 1024
#define NHEAD 16
#define SEQ 2048
#define QSTR 3072   // fused qkv row stride

// ---------------- scratch (device globals; no allocs allowed) ----------------
static __device__ float g_qkv[MTOK * QSTR];      // [q | k | v] fused
static __device__ float g_a[MTOK * DDIM];
static __device__ float g_attn[MTOK * DDIM];
static __device__ float g_gate[MTOK * DDIM];
static __device__ float g_lam[MTOK * NHEAD];
static __device__ float g_gam[MTOK * NHEAD];
static __device__ __half g_xh[MTOK * DDIM];
static __device__ __half g_g1h[MTOK * 64];
static __device__ __half g_normedh[MTOK * DDIM];
static __device__ __half g_wqkvt[3 * DDIM * DDIM];
static __device__ __half g_wot[DDIM * DDIM];
static __device__ __half g_wg1t[64 * DDIM];
static __device__ __half g_wg2t[DDIM * 64];

__device__ __forceinline__ uint32_t smem_u32(const void* p) {
    uint32_t a;
    asm("{ .reg .u64 t; cvta.to.shared.u64 t, %1; cvt.u32.u64 %0, t; }" : "=r"(a) : "l"(p));
    return a;
}
__device__ __forceinline__ void cp16(uint32_t dst, const void* src, int valid) {
    int sz = valid ? 16 : 0;
    asm volatile("cp.async.cg.shared.global [%0], [%1], 16, %2;" :: "r"(dst), "l"(src), "r"(sz));
}
__device__ __forceinline__ void cp4(uint32_t dst, const void* src) {
    asm volatile("cp.async.ca.shared.global [%0], [%1], 4;" :: "r"(dst), "l"(src));
}

// ================= fp16 tensor-core GEMM: C = act(A @ Bt^T) =================
// Tile 128x128, K-tile 32, 4-stage cp.async (2-ahead), 2 CTAs/SM.
#define ROWB 80
#define STAGEB (128 * ROWB * 2)          // 20480
#define HG_SMEM (4 * STAGEB)             // 81920

__global__ __launch_bounds__(256, 2)
void hgemm(const __half* __restrict__ A, const __half* __restrict__ Bt,
           void* __restrict__ Cout, int Ntot, int K, int act, int outHalf)
{
    extern __shared__ __align__(128) char smem[];
    const uint32_t sb = smem_u32(smem);
    const int tid = threadIdx.x, lane = tid & 31, warp = tid >> 5;
    const int wm = warp >> 2, wn = warp & 3;
    const int g = lane >> 2, tig = lane & 3;
    const int m0 = blockIdx.y * 128, n0 = blockIdx.x * 128;
    const int NC = K >> 5;

    float acc[4][4][4];
#pragma unroll
    for (int mt = 0; mt < 4; ++mt)
#pragma unroll
        for (int nt = 0; nt < 4; ++nt)
#pragma unroll
            for (int j = 0; j < 4; ++j) acc[mt][nt][j] = 0.f;

#define LOAD_TILE(kt, ss) do { \
    uint32_t aB = sb + (ss) * STAGEB; \
    uint32_t bB = aB + 128 * ROWB; \
    _Pragma("unroll") \
    for (int i = 0; i < 2; ++i) { \
        int id = tid + i * 256; \
        int r = id >> 2, c = id & 3; \
        cp16(aB + r * ROWB + c * 16, A + (size_t)(m0 + r) * K + (kt) * 32 + c * 8, 1); \
        int nr = n0 + r; int ok = nr < Ntot; int nrc = ok ? nr : 0; \
        cp16(bB + r * ROWB + c * 16, Bt + (size_t)nrc * K + (kt) * 32 + c * 8, ok); \
    } \
} while (0)

#pragma unroll
    for (int p = 0; p < 3; ++p) {
        if (p < NC) LOAD_TILE(p, p);
        asm volatile("cp.async.commit_group;" ::: "memory");
    }

    for (int kt = 0; kt < NC; ++kt) {
        asm volatile("cp.async.wait_group 2;" ::: "memory");
        __syncthreads();
        int ln = kt + 3;
        if (ln < NC) LOAD_TILE(ln, ln & 3);
        asm volatile("cp.async.commit_group;" ::: "memory");

        uint32_t aB = sb + (kt & 3) * STAGEB;
        uint32_t bB = aB + 128 * ROWB;
#pragma unroll
        for (int s = 0; s < 2; ++s) {
            uint32_t af[4][4], bf[4][2];
#pragma unroll
            for (int mt = 0; mt < 4; ++mt) {
                uint32_t addr = aB + (wm * 64 + mt * 16 + (lane & 15)) * ROWB
                              + (2 * s + (lane >> 4)) * 16;
                asm volatile("ldmatrix.sync.aligned.m8n8.x4.shared.b16 {%0,%1,%2,%3}, [%4];"
                    : "=r"(af[mt][0]), "=r"(af[mt][1]), "=r"(af[mt][2]), "=r"(af[mt][3])
                    : "r"(addr));
            }
#pragma unroll
            for (int nt = 0; nt < 4; ++nt) {
                uint32_t addr = bB + (wn * 32 + nt * 8 + (lane & 7)) * ROWB
                              + (2 * s + ((lane >> 3) & 1)) * 16;
                asm volatile("ldmatrix.sync.aligned.m8n8.x2.shared.b16 {%0,%1}, [%2];"
                    : "=r"(bf[nt][0]), "=r"(bf[nt][1]) : "r"(addr));
            }
#pragma unroll
            for (int mt = 0; mt < 4; ++mt)
#pragma unroll
                for (int nt = 0; nt < 4; ++nt) {
                    asm volatile(
                        "mma.sync.aligned.m16n8k16.row.col.f32.f16.f16.f32 "
                        "{%0,%1,%2,%3}, {%4,%5,%6,%7}, {%8,%9}, {%0,%1,%2,%3};"
                        : "+f"(acc[mt][nt][0]), "+f"(acc[mt][nt][1]),
                          "+f"(acc[mt][nt][2]), "+f"(acc[mt][nt][3])
                        : "r"(af[mt][0]), "r"(af[mt][1]), "r"(af[mt][2]), "r"(af[mt][3]),
                          "r"(bf[nt][0]), "r"(bf[nt][1]));
                }
        }
        __syncthreads();
    }
#undef LOAD_TILE

    float* Cf = (float*)Cout;
    __half* Ch = (__half*)Cout;
#pragma unroll
    for (int mt = 0; mt < 4; ++mt) {
        int row = m0 + wm * 64 + mt * 16 + g;
#pragma unroll
        for (int nt = 0; nt < 4; ++nt) {
            int col = n0 + wn * 32 + nt * 8 + tig * 2;
            if (col < Ntot) {
                float c0 = acc[mt][nt][0], c1 = acc[mt][nt][1];
                float c2 = acc[mt][nt][2], c3 = acc[mt][nt][3];
                if (act == 1) {
                    c0 = c0 / (1.f + expf(-c0)); c1 = c1 / (1.f + expf(-c1));
                    c2 = c2 / (1.f + expf(-c2)); c3 = c3 / (1.f + expf(-c3));
                } else if (act == 2) {
                    c0 = 1.f / (1.f + expf(-c0)); c1 = 1.f / (1.f + expf(-c1));
                    c2 = 1.f / (1.f + expf(-c2)); c3 = 1.f / (1.f + expf(-c3));
                }
                if (outHalf) {
                    *(__half2*)&Ch[(size_t)row * Ntot + col]       = __floats2half2_rn(c0, c1);
                    *(__half2*)&Ch[(size_t)(row + 8) * Ntot + col] = __floats2half2_rn(c2, c3);
                } else {
                    *(float2*)&Cf[(size_t)row * Ntot + col]       = make_float2(c0, c1);
                    *(float2*)&Cf[(size_t)(row + 8) * Ntot + col] = make_float2(c2, c3);
                }
            }
        }
    }
}

// ================= float -> half =================
__global__ void k_f2h(const float* __restrict__ S, __half* __restrict__ D, int n)
{
    int i = (blockIdx.x * 256 + threadIdx.x) * 4;
    if (i < n) {
        float4 f = *(const float4*)&S[i];
        *(__half2*)&D[i]     = __floats2half2_rn(f.x, f.y);
        *(__half2*)&D[i + 2] = __floats2half2_rn(f.z, f.w);
    }
}

// ================= all weight transposes+convert in ONE launch =================
__global__ void k_tr_all(const float* __restrict__ Wq, const float* __restrict__ Wk,
                         const float* __restrict__ Wv, const float* __restrict__ Wo,
                         const float* __restrict__ Wg1, const float* __restrict__ Wg2,
                         __half* __restrict__ wqkvt, __half* __restrict__ wot,
                         __half* __restrict__ wg1t, __half* __restrict__ wg2t)
{
    __shared__ float t[32][33];
    int blk = blockIdx.x;
    const float* S; __half* D; int R, C, tile;
    if (blk < 3072) {
        int seg = blk >> 10; tile = blk & 1023;
        S = (seg == 0) ? Wq : (seg == 1) ? Wk : Wv;
        D = wqkvt + (size_t)seg * DDIM * DDIM; R = DDIM; C = DDIM;
    } else if (blk < 4096) { tile = blk - 3072; S = Wo;  D = wot;  R = DDIM; C = DDIM; }
    else if (blk < 4160)   { tile = blk - 4096; S = Wg1; D = wg1t; R = DDIM; C = 64; }
    else                   { tile = blk - 4160; S = Wg2; D = wg2t; R = 64;   C = DDIM; }
    int tiles_x = C >> 5;
    int c0 = (tile % tiles_x) * 32, r0 = (tile / tiles_x) * 32;
    int x = threadIdx.x, y = threadIdx.y;   // 32 x 8
#pragma unroll
    for (int i = 0; i < 32; i += 8) t[y + i][x] = S[(size_t)(r0 + y + i) * C + c0 + x];
    __syncthreads();
#pragma unroll
    for (int i = 0; i < 32; i += 8)
        D[(size_t)(c0 + y + i) * R + r0 + x] = __float2half_rn(t[x][y + i]);
}

// ================= per-token f / gamma projections (fp32) =================
__global__ void k_fgamma(const float* __restrict__ x, const float* __restrict__ Wf,
                         const float* __restrict__ Wg, float* __restrict__ lam,
                         float* __restrict__ gam)
{
    __shared__ float xs[16][33];
    __shared__ float Ws[32][32];
    int t0 = blockIdx.x * 16;
    int tid = threadIdx.x;      // 256
    int c = tid & 31, tg = tid >> 5;
    float acc[2] = {0.f, 0.f};

    for (int k0 = 0; k0 < DDIM; k0 += 32) {
        __syncthreads();
#pragma unroll
        for (int i = 0; i < 2; ++i) {
            int idx = tid + i * 256;
            int tt = idx >> 5, kk = idx & 31;
            xs[tt][kk] = x[(size_t)(t0 + tt) * DDIM + k0 + kk];
        }
#pragma unroll
        for (int i = 0; i < 4; ++i) {
            int idx = tid + i * 256;
            int kr = idx >> 5, col = idx & 31;
            Ws[kr][col] = (col < 16) ? Wf[(k0 + kr) * NHEAD + col]
                                     : Wg[(k0 + kr) * NHEAD + (col - 16)];
        }
        __syncthreads();
#pragma unroll 8
        for (int kk = 0; kk < 32; ++kk) {
            float w = Ws[kk][c];
            acc[0] = fmaf(xs[tg * 2][kk], w, acc[0]);
            acc[1] = fmaf(xs[tg * 2 + 1][kk], w, acc[1]);
        }
    }
#pragma unroll
    for (int i = 0; i < 2; ++i) {
        int t = t0 + tg * 2 + i;
        float sg = 1.f / (1.f + expf(-acc[i]));
        if (c < 16) lam[t * NHEAD + c] = sg;
        else        gam[t * NHEAD + (c - 16)] = -sg;
    }
}

// ================= l2norm(k in qkv) per head; a = k_norm * gamma * lambda =================
__global__ void k_norm_a(float* __restrict__ qkv, const float* __restrict__ lam,
                         const float* __restrict__ gam, float* __restrict__ a)
{
    int t = blockIdx.x;
    int w = threadIdx.x >> 5;
    int lane = threadIdx.x & 31;
    size_t kb = (size_t)t * QSTR + DDIM + w * 64;
    float k0 = qkv[kb + lane], k1 = qkv[kb + lane + 32];
    float ss = k0 * k0 + k1 * k1;
#pragma unroll
    for (int o = 16; o; o >>= 1) ss += __shfl_xor_sync(0xffffffffu, ss, o);
    float inv = 1.f / fmaxf(sqrtf(ss), 1e-12f);
    float c = gam[t * NHEAD + w] * lam[t * NHEAD + w];
    float kn0 = k0 * inv, kn1 = k1 * inv;
    qkv[kb + lane] = kn0;               qkv[kb + lane + 32] = kn1;
    size_t ab = (size_t)t * DDIM + w * 64;
    a[ab + lane] = kn0 * c;             a[ab + lane + 32] = kn1 * c;
}

// ================= delta-rule scan =================
// 128 blocks = 32 (b,h) x 4 quarters; 128 thr = 16 cols x 8 subs.
// cp.async double-buffered tiles + REGISTER software pipeline within the tile:
// token t+1's a/k/q/lam/v prefetched from smem while computing token t, keeping
// LDS latency off the serial chain.
__global__ __launch_bounds__(128)
void k_scan(const float* __restrict__ qkv, const float* __restrict__ a,
            const float* __restrict__ lamArr, float* __restrict__ o)
{
    __shared__ __align__(16) float qs[2][16][64];
    __shared__ __align__(16) float ks[2][16][64];
    __shared__ __align__(16) float as_[2][16][64];
    __shared__ __align__(16) float vs[2][16][16];
    __shared__ float lm[2][16];

    const int blk = blockIdx.x;           // 0..127
    const int bh = blk >> 2, quarter = blk & 3;
    const int b = bh >> 4, h = bh & 15;
    const int tid = threadIdx.x;          // 0..127
    const int col = tid >> 3;             // 0..15
    const int sub = tid & 7;              // 0..7
    const int tok0 = b * SEQ;
    const int hoff = h * 64;

    const uint32_t qsB = smem_u32(&qs[0][0][0]);
    const uint32_t ksB = smem_u32(&ks[0][0][0]);
    const uint32_t asB = smem_u32(&as_[0][0][0]);
    const uint32_t vsB = smem_u32(&vs[0][0][0]);
    const uint32_t lmB = smem_u32(&lm[0][0]);

#define SC_LOAD(stg, buf) do { \
    int tb_ = tok0 + (stg) * 16; \
    _Pragma("unroll") \
    for (int i = 0; i < 2; ++i) { \
        int idx = tid + i * 128; \
        int tt = idx >> 4, c4 = idx & 15; \
        uint32_t so = (uint32_t)(((buf) * 16 + tt) * 64 + c4 * 4) * 4; \
        const float* qrow = qkv + (size_t)(tb_ + tt) * QSTR + hoff + c4 * 4; \
        cp16(qsB + so, qrow, 1); \
        cp16(ksB + so, qrow + DDIM, 1); \
        cp16(asB + so, a + (size_t)(tb_ + tt) * DDIM + hoff + c4 * 4, 1); \
    } \
    if (tid < 64) { \
        int tt = tid >> 2, c4 = tid & 3; \
        uint32_t so = (uint32_t)(((buf) * 16 + tt) * 16 + c4 * 4) * 4; \
        cp16(vsB + so, qkv + (size_t)(tb_ + tt) * QSTR + 2 * DDIM + hoff + quarter * 16 + c4 * 4, 1); \
    } \
    if (tid < 16) \
        cp4(lmB + (uint32_t)((buf) * 16 + tid) * 4, lamArr + (size_t)(tb_ + tid) * NHEAD + h); \
} while (0)

#define LD_TOK(tt_, buf_) do { \
    na0 = *(const float4*)&as_[buf_][tt_][sub * 8]; \
    na1 = *(const float4*)&as_[buf_][tt_][sub * 8 + 4]; \
    nk0 = *(const float4*)&ks[buf_][tt_][sub * 8]; \
    nk1 = *(const float4*)&ks[buf_][tt_][sub * 8 + 4]; \
    nq0 = *(const float4*)&qs[buf_][tt_][sub * 8]; \
    nq1 = *(const float4*)&qs[buf_][tt_][sub * 8 + 4]; \
    nl = lm[buf_][tt_]; \
    nv = vs[buf_][tt_][col]; \
} while (0)

    float s[8];
#pragma unroll
    for (int j = 0; j < 8; ++j) s[j] = 0.f;

    float4 na0, na1, nk0, nk1, nq0, nq1;
    float nl, nv;

    SC_LOAD(0, 0);
    asm volatile("cp.async.commit_group;" ::: "memory");
    asm volatile("cp.async.wait_group 0;" ::: "memory");
    __syncthreads();
    LD_TOK(0, 0);

    const int NT = SEQ / 16;
    for (int st = 0; st < NT; ++st) {
        const int buf = st & 1;
        if (st + 1 < NT) SC_LOAD(st + 1, buf ^ 1);
        asm volatile("cp.async.commit_group;" ::: "memory");

        const int tb = tok0 + st * 16;
#pragma unroll
        for (int tt = 0; tt < 16; ++tt) {
            // current token regs (renamed from prefetch)
            float4 ca0 = na0, ca1 = na1, ck0 = nk0, ck1 = nk1, cq0 = nq0, cq1 = nq1;
            float l = nl, cv = nv;
            if (tt < 15) LD_TOK(tt + 1, buf);   // prefetch next token (off-chain)
            // d = a . s
            float d0 = ca0.x * s[0] + ca0.y * s[1] + ca0.z * s[2] + ca0.w * s[3];
            float d1 = ca1.x * s[4] + ca1.y * s[5] + ca1.z * s[6] + ca1.w * s[7];
            float dp = d0 + d1;
            dp += __shfl_xor_sync(0xffffffffu, dp, 1);
            dp += __shfl_xor_sync(0xffffffffu, dp, 2);
            dp += __shfl_xor_sync(0xffffffffu, dp, 4);
            float u = fmaf(l, dp, cv);
            s[0] = fmaf(ck0.x, u, l * s[0]); s[1] = fmaf(ck0.y, u, l * s[1]);
            s[2] = fmaf(ck0.z, u, l * s[2]); s[3] = fmaf(ck0.w, u, l * s[3]);
            s[4] = fmaf(ck1.x, u, l * s[4]); s[5] = fmaf(ck1.y, u, l * s[5]);
            s[6] = fmaf(ck1.z, u, l * s[6]); s[7] = fmaf(ck1.w, u, l * s[7]);
            float o0 = cq0.x * s[0] + cq0.y * s[1] + cq0.z * s[2] + cq0.w * s[3];
            float o1 = cq1.x * s[4] + cq1.y * s[5] + cq1.z * s[6] + cq1.w * s[7];
            float op = o0 + o1;
            op += __shfl_xor_sync(0xffffffffu, op, 1);
            op += __shfl_xor_sync(0xffffffffu, op, 2);
            op += __shfl_xor_sync(0xffffffffu, op, 4);
            if (sub == 0)
                o[(size_t)(tb + tt) * DDIM + hoff + quarter * 16 + col] = op;
        }
        asm volatile("cp.async.wait_group 0;" ::: "memory");
        __syncthreads();
        if (st + 1 < NT) LD_TOK(0, buf ^ 1);    // first token of next tile
    }
#undef SC_LOAD
#undef LD_TOK
}

// ================= gate-multiply + LayerNorm -> half =================
__global__ void k_ln(const float* __restrict__ attn, const float* __restrict__ gate,
                     const float* __restrict__ nw, __half* __restrict__ outh)
{
    __shared__ float red[32];
    int t = blockIdx.x;
    int tid = threadIdx.x;  // 256
    int lane = tid & 31, w = tid >> 5;
    float y[4];
    float sm = 0.f;
#pragma unroll
    for (int i = 0; i < 4; ++i) {
        int j = tid + i * 256;
        y[i] = attn[(size_t)t * DDIM + j] * gate[(size_t)t * DDIM + j];
        sm += y[i];
    }
#pragma unroll
    for (int o = 16; o; o >>= 1) sm += __shfl_xor_sync(0xffffffffu, sm, o);
    if (lane == 0) red[w] = sm;
    __syncthreads();
    if (w == 0) {
        float v2 = (lane < 8) ? red[lane] : 0.f;
#pragma unroll
        for (int o = 4; o; o >>= 1) v2 += __shfl_xor_sync(0xffffffffu, v2, o);
        if (lane == 0) red[0] = v2;
    }
    __syncthreads();
    float mu = red[0] * (1.f / DDIM);
    __syncthreads();
    float vsum = 0.f;
#pragma unroll
    for (int i = 0; i < 4; ++i) { float d = y[i] - mu; vsum += d * d; }
#pragma unroll
    for (int o = 16; o; o >>= 1) vsum += __shfl_xor_sync(0xffffffffu, vsum, o);
    if (lane == 0) red[w] = vsum;
    __syncthreads();
    if (w == 0) {
        float v2 = (lane < 8) ? red[lane] : 0.f;
#pragma unroll
        for (int o = 4; o; o >>= 1) v2 += __shfl_xor_sync(0xffffffffu, v2, o);
        if (lane == 0) red[0] = v2;
    }
    __syncthreads();
    float inv = rsqrtf(red[0] * (1.f / DDIM) + 1e-5f);
#pragma unroll
    for (int i = 0; i < 4; ++i) {
        int j = tid + i * 256;
        outh[(size_t)t * DDIM + j] = __float2half_rn((y[i] - mu) * inv * nw[j]);
    }
}

// ================= launch =================
extern "C" void kernel_launch(void* const* d_in, const int* in_sizes, int n_in,
                              void* d_out, int out_size)
{
    const float* x      = (const float*)d_in[0];
    const float* Wq     = (const float*)d_in[1];
    const float* Wk     = (const float*)d_in[2];
    const float* Wv     = (const float*)d_in[3];
    const float* Wgamma = (const float*)d_in[4];
    const float* Wf     = (const float*)d_in[5];
    const float* Wg1    = (const float*)d_in[6];
    const float* Wg2    = (const float*)d_in[7];
    const float* Wo     = (const float*)d_in[8];
    const float* nw     = (const float*)d_in[9];
    float* out = (float*)d_out;

    float *qkv, *a, *attn, *gate, *lam, *gam;
    __half *xh, *g1h, *normedh, *wqkvt, *wot, *wg1t, *wg2t;
    cudaGetSymbolAddress((void**)&qkv, g_qkv);
    cudaGetSymbolAddress((void**)&a, g_a);
    cudaGetSymbolAddress((void**)&attn, g_attn);
    cudaGetSymbolAddress((void**)&gate, g_gate);
    cudaGetSymbolAddress((void**)&lam, g_lam);
    cudaGetSymbolAddress((void**)&gam, g_gam);
    cudaGetSymbolAddress((void**)&xh, g_xh);
    cudaGetSymbolAddress((void**)&g1h, g_g1h);
    cudaGetSymbolAddress((void**)&normedh, g_normedh);
    cudaGetSymbolAddress((void**)&wqkvt, g_wqkvt);
    cudaGetSymbolAddress((void**)&wot, g_wot);
    cudaGetSymbolAddress((void**)&wg1t, g_wg1t);
    cudaGetSymbolAddress((void**)&wg2t, g_wg2t);

    cudaFuncSetAttribute(hgemm, cudaFuncAttributeMaxDynamicSharedMemorySize, HG_SMEM);

    // 1: convert x
    k_f2h<<<MTOK * DDIM / (256 * 4), 256>>>(x, xh, MTOK * DDIM);
    // 2: all weight transposes fused
    k_tr_all<<<4224, dim3(32, 8)>>>(Wq, Wk, Wv, Wo, Wg1, Wg2, wqkvt, wot, wg1t, wg2t);
    // 3: lam/gamma projections
    k_fgamma<<<MTOK / 16, 256>>>(x, Wf, Wgamma, lam, gam);
    // 4: fused QKV GEMM (profiled slot)
    hgemm<<<dim3(24, 32), 256, HG_SMEM>>>(xh, wqkvt, qkv, QSTR, DDIM, 1, 0);
    // 5: l2norm + a
    k_norm_a<<<MTOK, 512>>>(qkv, lam, gam, a);
    // 6: delta-rule scan
    k_scan<<<128, 128>>>(qkv, a, lam, attn);
    // 7: g1 = x @ Wg1 (half out)
    hgemm<<<dim3(1, 32), 256, HG_SMEM>>>(xh, wg1t, g1h, 64, DDIM, 0, 1);
    // 8: gate = sigmoid(g1 @ Wg2)
    hgemm<<<dim3(8, 32), 256, HG_SMEM>>>(g1h, wg2t, gate, DDIM, 64, 2, 0);
    // 9: gated LayerNorm -> half
    k_ln<<<MTOK, 256>>>(attn, gate, nw, normedh);
    // 10: out = normed @ Wo
    hgemm<<<dim3(8, 32), 256, HG_SMEM>>>(normedh, wot, out, DDIM, DDIM, 0, 0);
}